// round 3
// baseline (speedup 1.0000x reference)
#include <cuda_runtime.h>
#include <cuda_bf16.h>
#include <cstdint>
#include <cstddef>

#define SEQ    512
#define BATCH  32
#define IND    1024
#define HID    1024
#define LAYERS 4
#define G4H    (4*HID)
#define SB     (SEQ*BATCH)       // 16384
#define SBH    (SEQ*BATCH*HID)   // 16777216

// ---------------- device scratch (no allocations allowed) ----------------
__device__ float g_gates[(size_t)SB * G4H];      // 256 MB: x-projection + biases per layer
__device__ float g_ybuf[2][SBH];                 // 128 MB: layer output ping-pong
__device__ float g_hbuf[2][HID * BATCH];         // transposed h: [k][b], double buffered
__device__ __align__(128) unsigned int g_bar_count;
__device__ __align__(128) unsigned int g_bar_gen;

// ---------------- f32x2 packed-math helpers (sm_103a FFMA2 path) ----------------
typedef unsigned long long u64;

__device__ __forceinline__ u64 pk2(float lo, float hi) {
    u64 r; asm("mov.b64 %0, {%1, %2};" : "=l"(r) : "f"(lo), "f"(hi)); return r;
}
__device__ __forceinline__ u64 dup2(float x) {
    u64 r; asm("mov.b64 %0, {%1, %1};" : "=l"(r) : "f"(x)); return r;
}
__device__ __forceinline__ u64 ffma2(u64 a, u64 b, u64 c) {
    u64 r; asm("fma.rn.f32x2 %0, %1, %2, %3;" : "=l"(r) : "l"(a), "l"(b), "l"(c)); return r;
}
__device__ __forceinline__ u64 fadd2(u64 a, u64 b) {
    u64 r; asm("add.rn.f32x2 %0, %1, %2;" : "=l"(r) : "l"(a), "l"(b)); return r;
}
__device__ __forceinline__ float2 up2(u64 a) {
    float2 v; asm("mov.b64 {%0, %1}, %2;" : "=f"(v.x), "=f"(v.y) : "l"(a)); return v;
}

__device__ __forceinline__ float sigm(float x) { return 1.f / (1.f + expf(-x)); }
// accurate tanh via exp (avoids fast-math tanh.approx 2^-11 error which could
// compound over 512 recurrent steps)
__device__ __forceinline__ float tanh_acc(float x) {
    float ax = fabsf(x);
    float e  = expf(-2.f * ax);
    float r  = (1.f - e) / (1.f + e);
    return x >= 0.f ? r : -r;
}

// ---------------- software grid barrier (all CTAs co-resident) ----------------
__device__ __forceinline__ void grid_barrier() {
    __syncthreads();
    if (threadIdx.x == 0) {
        __threadfence();                       // release: my writes visible in L2
        volatile unsigned int* genp = &g_bar_gen;
        unsigned int old_gen = *genp;
        unsigned int arrived = atomicAdd(&g_bar_count, 1u);
        if (arrived == gridDim.x - 1) {
            g_bar_count = 0;
            __threadfence();
            atomicAdd(&g_bar_gen, 1u);
        } else {
            while (*genp == old_gen) { }
        }
        __threadfence();                       // acquire: order subsequent loads after spin
    }
    __syncthreads();
}

// ================================================================
// Kernel 1: x_gates GEMM.  C[m][n] = sum_k A[m][k] * W[n][k] + bih[n] + bhh[n]
// A: [16384, 1024] row-major (K contiguous), W: [4096, 1024] row-major (K contiguous)
// Tile 128x128x32, 256 threads, 8x8 microtile via FFMA2.
// Transposed smem stores have ~8-way bank conflicts but the crossbar time
// (~3.6K cyc/tile incl. loads) stays below the FFMA2 compute time (~4.1K
// cyc/SMSP/tile) — compute-bound by model; revisit only if ncu disagrees.
// ================================================================
__global__ void __launch_bounds__(256, 2)
xgates_gemm(const float* __restrict__ A, const float* __restrict__ W,
            const float* __restrict__ bih, const float* __restrict__ bhh,
            float* __restrict__ C)
{
    __shared__ __align__(16) float As[32][128];
    __shared__ __align__(16) float Bs[32][128];

    const int tid = threadIdx.x;
    const int m0  = blockIdx.y * 128;
    const int n0  = blockIdx.x * 128;
    const int tx  = tid & 15;
    const int ty  = tid >> 4;
    const int lk  = tid & 7;    // float4 column in K
    const int lm  = tid >> 3;   // row 0..31

    const float* Ag = A + (size_t)m0 * IND;
    const float* Wg = W + (size_t)n0 * IND;

    u64 acc[8][4];
#pragma unroll
    for (int m = 0; m < 8; m++)
#pragma unroll
        for (int p = 0; p < 4; p++) acc[m][p] = 0ull;

    for (int k0 = 0; k0 < IND; k0 += 32) {
#pragma unroll
        for (int i = 0; i < 4; i++) {
            int row = lm + i * 32;
            float4 av = *(const float4*)(Ag + (size_t)row * IND + k0 + lk * 4);
            As[lk*4+0][row] = av.x; As[lk*4+1][row] = av.y;
            As[lk*4+2][row] = av.z; As[lk*4+3][row] = av.w;
            float4 wv = *(const float4*)(Wg + (size_t)row * IND + k0 + lk * 4);
            Bs[lk*4+0][row] = wv.x; Bs[lk*4+1][row] = wv.y;
            Bs[lk*4+2][row] = wv.z; Bs[lk*4+3][row] = wv.w;
        }
        __syncthreads();
#pragma unroll
        for (int k = 0; k < 32; k++) {
            float4 a0 = *(const float4*)&As[k][ty * 8];
            float4 a1 = *(const float4*)&As[k][ty * 8 + 4];
            ulonglong2 bA = *(const ulonglong2*)&Bs[k][tx * 8];
            ulonglong2 bB = *(const ulonglong2*)&Bs[k][tx * 8 + 4];
            float am[8] = {a0.x, a0.y, a0.z, a0.w, a1.x, a1.y, a1.z, a1.w};
#pragma unroll
            for (int m = 0; m < 8; m++) {
                u64 ad = dup2(am[m]);
                acc[m][0] = ffma2(ad, bA.x, acc[m][0]);
                acc[m][1] = ffma2(ad, bA.y, acc[m][1]);
                acc[m][2] = ffma2(ad, bB.x, acc[m][2]);
                acc[m][3] = ffma2(ad, bB.y, acc[m][3]);
            }
        }
        __syncthreads();
    }

    float bias[8];
#pragma unroll
    for (int i = 0; i < 8; i++) {
        int n = n0 + tx * 8 + i;
        bias[i] = bih[n] + bhh[n];
    }
#pragma unroll
    for (int m = 0; m < 8; m++) {
        int row = m0 + ty * 8 + m;
        float2 p0 = up2(acc[m][0]);
        float2 p1 = up2(acc[m][1]);
        float2 p2 = up2(acc[m][2]);
        float2 p3 = up2(acc[m][3]);
        float4 o0 = make_float4(p0.x + bias[0], p0.y + bias[1], p1.x + bias[2], p1.y + bias[3]);
        float4 o1 = make_float4(p2.x + bias[4], p2.y + bias[5], p3.x + bias[6], p3.y + bias[7]);
        float* cp = C + (size_t)row * G4H + n0 + tx * 8;
        *(float4*)cp       = o0;
        *(float4*)(cp + 4) = o1;
    }
}

// ================================================================
// Kernel 2: persistent recurrence. 128 CTAs x 256 threads, 1 CTA/SM.
// CTA owns 8 hidden units; W_hh slice (32 gate rows x 1024) resident in smem
// packed as float4 (i,f,g,o) per (k, u). One grid barrier per timestep.
// Cross-CTA h traffic uses __ldcg/__stcg (L2-coherent; per-SM L1 is NOT
// coherent across CTAs and the double-buffered h lines would otherwise go
// stale with period-2 reuse).
// smem = 1024*9 float4 (W, padded) + 4*8*32 ulonglong2 (K-slice reduction)
// ================================================================
#define REC_SMEM (1024*9*16 + 4*8*32*16)   // 147456 + 16384 = 163840 B

__global__ void __launch_bounds__(256, 1)
lstm_recurrent(const float* __restrict__ gates,   // [512*32*4096]
               const float* __restrict__ Whh,     // [4096*1024]
               float* __restrict__ y,             // [512*32*1024]
               float* __restrict__ hlast,         // [32*1024]
               float* __restrict__ clast)         // [32*1024]
{
    extern __shared__ float smem[];
    float4*           Wsm4 = (float4*)smem;                       // [k*9 + u]
    const ulonglong2* Wsm2 = (const ulonglong2*)smem;             // same, as (IF, GO) pairs
    ulonglong2*       red2 = (ulonglong2*)(smem + 1024 * 9 * 4);  // [(ks*8+u)*32 + b]

    const int tid = threadIdx.x;
    const int cta = blockIdx.x;
    const int u0  = cta * 8;

    // preload W_hh slice: Wsm[k][u] = (Wi, Wf, Wg, Wo) for unit j=u0+u
    for (int i = tid; i < HID * 8; i += 256) {
        int k = i >> 3, u = i & 7;
        int j = u0 + u;
        float4 w;
        w.x = Whh[(size_t)(0 * HID + j) * HID + k];
        w.y = Whh[(size_t)(1 * HID + j) * HID + k];
        w.z = Whh[(size_t)(2 * HID + j) * HID + k];
        w.w = Whh[(size_t)(3 * HID + j) * HID + k];
        Wsm4[k * 9 + u] = w;
    }
    // zero h(t=0) buffer (32768 floats over 128 CTAs x 256 threads)
    __stcg(&g_hbuf[0][cta * 256 + tid], 0.f);
    grid_barrier();

    // GEMM-phase role: K-slice ks, unit uu, batch quad hb (b = hb*4..hb*4+3)
    const int ks = tid >> 6;
    const int r  = tid & 63;
    const int uu = r & 7;
    const int hb = r >> 3;
    // pointwise-phase role: one (b, unit) element per thread
    const int pb = tid & 31;
    const int pu = tid >> 5;
    const int pj = u0 + pu;

    float c_state = 0.f;

    for (int t = 0; t < SEQ; t++) {
        // prefetch this thread's x-gate biases (independent of h)
        const float* gbase = gates + (size_t)(t * BATCH + pb) * G4H + pj;
        float xg_i = gbase[0];
        float xg_f = gbase[HID];
        float xg_g = gbase[2 * HID];
        float xg_o = gbase[3 * HID];

        // partial GEMM over K slice: acc[(b, i|f)] and acc[(b, g|o)] as f32x2
        const float4* h4 = (const float4*)g_hbuf[t & 1];
        u64 aIF0 = 0, aIF1 = 0, aIF2 = 0, aIF3 = 0;
        u64 aGO0 = 0, aGO1 = 0, aGO2 = 0, aGO3 = 0;
        const int kbeg = ks << 8;
#pragma unroll 8
        for (int k = kbeg; k < kbeg + 256; k++) {
            float4 hv = __ldcg(&h4[(k << 3) + hb]);  // h[k][b0..b0+3], L2-coherent
            ulonglong2 wv = Wsm2[k * 9 + uu];        // (Wi,Wf), (Wg,Wo)
            u64 h0 = dup2(hv.x), h1 = dup2(hv.y), h2 = dup2(hv.z), h3 = dup2(hv.w);
            aIF0 = ffma2(h0, wv.x, aIF0); aGO0 = ffma2(h0, wv.y, aGO0);
            aIF1 = ffma2(h1, wv.x, aIF1); aGO1 = ffma2(h1, wv.y, aGO1);
            aIF2 = ffma2(h2, wv.x, aIF2); aGO2 = ffma2(h2, wv.y, aGO2);
            aIF3 = ffma2(h3, wv.x, aIF3); aGO3 = ffma2(h3, wv.y, aGO3);
        }
        {
            int base = (ks * 8 + uu) * 32 + (hb << 2);
            red2[base + 0] = make_ulonglong2(aIF0, aGO0);
            red2[base + 1] = make_ulonglong2(aIF1, aGO1);
            red2[base + 2] = make_ulonglong2(aIF2, aGO2);
            red2[base + 3] = make_ulonglong2(aIF3, aGO3);
        }
        __syncthreads();

        // pointwise: reduce 4 K-slices, add x-gates, apply LSTM cell
        u64 sIF = pk2(xg_i, xg_f);
        u64 sGO = pk2(xg_g, xg_o);
#pragma unroll
        for (int q = 0; q < 4; q++) {
            ulonglong2 v = red2[(q * 8 + pu) * 32 + pb];
            sIF = fadd2(sIF, v.x);
            sGO = fadd2(sGO, v.y);
        }
        float2 vif = up2(sIF);
        float2 vgo = up2(sGO);
        float gi = sigm(vif.x), gf = sigm(vif.y);
        float gg = tanh_acc(vgo.x), go = sigm(vgo.y);
        float cn = gf * c_state + gi * gg;
        float hn = go * tanh_acc(cn);
        c_state = cn;

        __stcg(&g_hbuf[(t + 1) & 1][pj * BATCH + pb], hn);       // transposed for next step
        y[(size_t)(t * BATCH + pb) * HID + pj] = hn;             // [S][B][H] layer output
        if (t == SEQ - 1) {
            hlast[pb * HID + pj] = hn;
            clast[pb * HID + pj] = cn;
        }
        grid_barrier();
    }
}

// ================================================================
// Host launch: 4 x (GEMM + persistent recurrence), graph-capturable.
// ================================================================
extern "C" void kernel_launch(void* const* d_in, const int* in_sizes, int n_in,
                              void* d_out, int out_size)
{
    const float* x   = (const float*)d_in[0];
    const float* Wih = (const float*)d_in[1];
    const float* Whh = (const float*)d_in[2];
    const float* bih = (const float*)d_in[3];
    const float* bhh = (const float*)d_in[4];

    float* out    = (float*)d_out;               // [512, 32, 1024]
    float* hstack = out + (size_t)SBH;           // [4, 32, 1024]
    float* cstack = hstack + (size_t)LAYERS * BATCH * HID;

    cudaFuncSetAttribute(lstm_recurrent, cudaFuncAttributeMaxDynamicSharedMemorySize, REC_SMEM);

    void* p;
    cudaGetSymbolAddress(&p, g_gates); float* gates = (float*)p;
    cudaGetSymbolAddress(&p, g_ybuf);  float* ybuf  = (float*)p;

    dim3 ggrid(G4H / 128, SB / 128);  // (32, 128)
    for (int l = 0; l < LAYERS; l++) {
        const float* A = (l == 0) ? x : ybuf + (size_t)((l - 1) & 1) * SBH;
        xgates_gemm<<<ggrid, 256>>>(A,
                                    Wih + (size_t)l * G4H * IND,
                                    bih + (size_t)l * G4H,
                                    bhh + (size_t)l * G4H,
                                    gates);
        float* yt = (l < LAYERS - 1) ? ybuf + (size_t)(l & 1) * SBH : out;
        lstm_recurrent<<<128, 256, REC_SMEM>>>(gates,
                                               Whh + (size_t)l * G4H * HID,
                                               yt,
                                               hstack + (size_t)l * BATCH * HID,
                                               cstack + (size_t)l * BATCH * HID);
    }
}